// round 9
// baseline (speedup 1.0000x reference)
#include <cuda_runtime.h>
#include <cuda_fp16.h>
#include <math.h>
#include <stdint.h>

#define HIDDEN  2048
#define NHEADS  16
#define HDIM    128
#define BATCH   2
#define SEQ     2048
#define MTOK    (BATCH * SEQ)   // 4096

#define NELEM_X ((size_t)MTOK * HIDDEN)     // 8388608
#define NELEM_W ((size_t)HIDDEN * HIDDEN)   // 4194304

// ---------------- scratch (static device globals) ---------------------------
__device__ __align__(16) float  g_q[NELEM_X];
__device__ __align__(16) float  g_k[NELEM_X];
__device__ __align__(16) __half g_xh[NELEM_X],  g_xl[NELEM_X];
__device__ __align__(16) __half g_wqh[NELEM_W], g_wql[NELEM_W];
__device__ __align__(16) __half g_wkh[NELEM_W], g_wkl[NELEM_W];
__device__ __align__(16) __half g_wvh[NELEM_W], g_wvl[NELEM_W];
__device__ __align__(16) __half g_woh[NELEM_W], g_wol[NELEM_W];
__device__ __align__(16) __half g_qh[NELEM_X],  g_ql[NELEM_X];
__device__ __align__(16) __half g_kh[NELEM_X],  g_kl[NELEM_X];
__device__ __align__(16) __half g_vh[NELEM_X],  g_vl[NELEM_X];
__device__ __align__(16) __half g_oh[NELEM_X],  g_ol[NELEM_X];

// ---------------- helpers ----------------------------------------------------
__device__ __forceinline__ void split2(float x, float y, uint32_t& hi, uint32_t& lo) {
    __half2 h = __float22half2_rn(make_float2(x, y));
    float2 b = __half22float2(h);
    __half2 l = __float22half2_rn(make_float2(x - b.x, y - b.y));
    hi = *(uint32_t*)&h;
    lo = *(uint32_t*)&l;
}
__device__ __forceinline__ void mma16816(float* c, const uint32_t* a,
                                         uint32_t b0, uint32_t b1) {
    asm volatile(
        "mma.sync.aligned.m16n8k16.row.col.f32.f16.f16.f32 "
        "{%0,%1,%2,%3}, {%4,%5,%6,%7}, {%8,%9}, {%0,%1,%2,%3};\n"
        : "+f"(c[0]), "+f"(c[1]), "+f"(c[2]), "+f"(c[3])
        : "r"(a[0]), "r"(a[1]), "r"(a[2]), "r"(a[3]), "r"(b0), "r"(b1));
}
__device__ __forceinline__ uint32_t smem_u32(const void* p) {
    uint32_t a;
    asm("{ .reg .u64 t; cvta.to.shared.u64 t, %1; cvt.u32.u64 %0, t; }"
        : "=r"(a) : "l"(p));
    return a;
}
#define CP16(dst, src) \
    asm volatile("cp.async.cg.shared.global [%0], [%1], 16;" \
                 :: "r"(dst), "l"(src) : "memory")
#define CP_COMMIT() asm volatile("cp.async.commit_group;" ::: "memory")
#define CP_WAIT0()  asm volatile("cp.async.wait_group 0;"  ::: "memory")

#define LDSM_X4(r0, r1, r2, r3, a)                                          \
    asm volatile("ldmatrix.sync.aligned.m8n8.x4.shared.b16 {%0,%1,%2,%3}, [%4];" \
                 : "=r"(r0), "=r"(r1), "=r"(r2), "=r"(r3) : "r"(a))
#define LDSM_X4T(r0, r1, r2, r3, a)                                         \
    asm volatile("ldmatrix.sync.aligned.m8n8.x4.trans.shared.b16 {%0,%1,%2,%3}, [%4];" \
                 : "=r"(r0), "=r"(r1), "=r"(r2), "=r"(r3) : "r"(a))

// ============================================================================
// split kernels
// ============================================================================
__global__ __launch_bounds__(256) void split_kernel(const float4* __restrict__ src,
                                                    uint2* __restrict__ hi,
                                                    uint2* __restrict__ lo, int n4) {
    const int i = blockIdx.x * 256 + threadIdx.x;
    if (i >= n4) return;
    const float4 v = src[i];
    uint32_t h0, l0, h1, l1;
    split2(v.x, v.y, h0, l0);
    split2(v.z, v.w, h1, l1);
    hi[i] = make_uint2(h0, h1);
    lo[i] = make_uint2(l0, l1);
}

// all 4 weights in one launch (z selects)
__global__ __launch_bounds__(256) void split4_kernel(
    const float4* __restrict__ s0, const float4* __restrict__ s1,
    const float4* __restrict__ s2, const float4* __restrict__ s3,
    uint2* __restrict__ h0, uint2* __restrict__ l0,
    uint2* __restrict__ h1, uint2* __restrict__ l1,
    uint2* __restrict__ h2, uint2* __restrict__ l2,
    uint2* __restrict__ h3, uint2* __restrict__ l3, int n4) {
    const int i = blockIdx.x * 256 + threadIdx.x;
    if (i >= n4) return;
    const int z = blockIdx.y;
    const float4* src = (z == 0) ? s0 : (z == 1) ? s1 : (z == 2) ? s2 : s3;
    uint2* hi = (z == 0) ? h0 : (z == 1) ? h1 : (z == 2) ? h2 : h3;
    uint2* lo = (z == 0) ? l0 : (z == 1) ? l1 : (z == 2) ? l2 : l3;
    const float4 v = src[i];
    uint32_t a0, b0, a1, b1;
    split2(v.x, v.y, a0, b0);
    split2(v.z, v.w, a1, b1);
    hi[i] = make_uint2(a0, a1);
    lo[i] = make_uint2(b0, b1);
}

// ============================================================================
// GEMM core (NT): 128x128 tile, BK=32, 256 threads, cp.async double-buffered,
// fragment loads via ldmatrix.x4.
// smem stage = {Ah,Al,Bh,Bl} x 128row x 20 words = 40960 B; 2 stages.
// ============================================================================
#define GK_SMEM 81920

__device__ __forceinline__ void g_fill(uint32_t sb,
                                       const __half* __restrict__ Ah,
                                       const __half* __restrict__ Al,
                                       const __half* __restrict__ Bh,
                                       const __half* __restrict__ Bl,
                                       int bm, int bn, int k0) {
    const int tid = threadIdx.x;
    const int row = tid >> 1, hf = tid & 1;
    const uint32_t off = (uint32_t)(row * 20 + hf * 8) * 4;
    const size_t ra = ((size_t)(bm + row) << 11) + k0 + hf * 16;
    const size_t rb = ((size_t)(bn + row) << 11) + k0 + hf * 16;
    CP16(sb + off,         Ah + ra); CP16(sb + off + 16,         Ah + ra + 8);
    CP16(sb + 10240 + off, Al + ra); CP16(sb + 10240 + off + 16, Al + ra + 8);
    CP16(sb + 20480 + off, Bh + rb); CP16(sb + 20480 + off + 16, Bh + rb + 8);
    CP16(sb + 30720 + off, Bl + rb); CP16(sb + 30720 + off + 16, Bl + rb + 8);
}

__device__ __forceinline__ void g_compute(uint32_t s, float acc[4][4][4],
                                          int wm, int wn, int lane) {
    // A x4: lanes 0-15 rows (l&15) @k0-chunk, lanes 16-31 same rows @k8-chunk
    const uint32_t aln = (uint32_t)((lane & 15) * 80 + (lane >> 4) * 16);
    // B x4: lanes 0-7 n0-7@k0, 8-15 n0-7@k8, 16-23 n8-15@k0, 24-31 n8-15@k8
    const uint32_t bln = (uint32_t)(((lane & 7) | ((lane >> 1) & 8)) * 80 +
                                    ((lane >> 3) & 1) * 16);
    const uint32_t sAh = s + (uint32_t)(wm * 64 * 80) + aln;
    const uint32_t sAl = sAh + 10240;
    const uint32_t sBh = s + 20480 + (uint32_t)(wn * 32 * 80) + bln;
    const uint32_t sBl = sBh + 10240;

#pragma unroll
    for (int ks = 0; ks < 2; ks++) {
        const uint32_t ko = ks * 32;
        uint32_t ah[4][4], al[4][4], bh[2][4], bl[2][4];
#pragma unroll
        for (int mf = 0; mf < 4; mf++) {
            LDSM_X4(ah[mf][0], ah[mf][1], ah[mf][2], ah[mf][3],
                    sAh + mf * 1280 + ko);
            LDSM_X4(al[mf][0], al[mf][1], al[mf][2], al[mf][3],
                    sAl + mf * 1280 + ko);
        }
#pragma unroll
        for (int p = 0; p < 2; p++) {
            LDSM_X4(bh[p][0], bh[p][1], bh[p][2], bh[p][3], sBh + p * 1280 + ko);
            LDSM_X4(bl[p][0], bl[p][1], bl[p][2], bl[p][3], sBl + p * 1280 + ko);
        }
#pragma unroll
        for (int p = 0; p < 2; p++) {
#pragma unroll
            for (int hh = 0; hh < 2; hh++) {
                const int nf = p * 2 + hh;
                const uint32_t b0 = bh[p][hh * 2], b1 = bh[p][hh * 2 + 1];
                const uint32_t c0 = bl[p][hh * 2], c1 = bl[p][hh * 2 + 1];
#pragma unroll
                for (int mf = 0; mf < 4; mf++) {
                    mma16816(acc[mf][nf], ah[mf], b0, b1);
                    mma16816(acc[mf][nf], al[mf], b0, b1);
                    mma16816(acc[mf][nf], ah[mf], c0, c1);
                }
            }
        }
    }
}

// Fused QKV GEMM: z=0 -> q fp32 [B,H,S,D]; z=1 -> k fp32; z=2 -> v split fp16.
__global__ __launch_bounds__(256, 2) void qkv_gemm(
    const __half* __restrict__ xh, const __half* __restrict__ xl,
    const __half* __restrict__ wqh, const __half* __restrict__ wql,
    const __half* __restrict__ wkh, const __half* __restrict__ wkl,
    const __half* __restrict__ wvh, const __half* __restrict__ wvl,
    float* __restrict__ q, float* __restrict__ k,
    uint32_t* __restrict__ vh, uint32_t* __restrict__ vl) {
    extern __shared__ uint32_t dyn[];
    const int tid = threadIdx.x;
    const int w = tid >> 5, lane = tid & 31;
    const int g = lane >> 2, tg = lane & 3;
    const int wm = w >> 2, wn = w & 3;
    const int bm = blockIdx.y * 128, bn = blockIdx.x * 128;
    const int z = blockIdx.z;

    const __half* Bh = (z == 0) ? wqh : (z == 1) ? wkh : wvh;
    const __half* Bl = (z == 0) ? wql : (z == 1) ? wkl : wvl;

    float acc[4][4][4];
#pragma unroll
    for (int i = 0; i < 4; i++)
#pragma unroll
        for (int j = 0; j < 4; j++)
#pragma unroll
            for (int c = 0; c < 4; c++) acc[i][j][c] = 0.0f;

    const uint32_t sb = smem_u32(dyn);
    g_fill(sb, xh, xl, Bh, Bl, bm, bn, 0);
    CP_COMMIT();

    for (int i = 0; i < 64; i++) {
        CP_WAIT0();
        __syncthreads();
        if (i + 1 < 64) {
            g_fill(sb + ((i + 1) & 1) * 40960u, xh, xl, Bh, Bl, bm, bn, (i + 1) * 32);
            CP_COMMIT();
        }
        g_compute(sb + (i & 1) * 40960u, acc, wm, wn, lane);
    }

#pragma unroll
    for (int mf = 0; mf < 4; mf++) {
#pragma unroll
        for (int nf = 0; nf < 4; nf++) {
            const int n = bn + wn * 32 + nf * 8 + tg * 2;
            const int h = n >> 7, d = n & 127;
            const int m0 = bm + wm * 64 + mf * 16 + g;
            const int b = m0 >> 11, s0 = m0 & (SEQ - 1);
            if (z == 2) {
                const size_t widx =
                    (((size_t)(b * NHEADS + h) * SEQ + s0) << 6) + (d >> 1);
                uint32_t hi, lo;
                split2(acc[mf][nf][0], acc[mf][nf][1], hi, lo);
                vh[widx] = hi; vl[widx] = lo;
                split2(acc[mf][nf][2], acc[mf][nf][3], hi, lo);
                vh[widx + 512] = hi; vl[widx + 512] = lo;
            } else {
                float* C = (z == 0) ? q : k;
                const size_t base =
                    (((size_t)(b * NHEADS + h) * SEQ + s0) << 7) + d;
                *(float2*)&C[base] = make_float2(acc[mf][nf][0], acc[mf][nf][1]);
                *(float2*)&C[base + (8u << 7)] =
                    make_float2(acc[mf][nf][2], acc[mf][nf][3]);
            }
        }
    }
}

__global__ __launch_bounds__(256, 2) void out_gemm(
    const __half* __restrict__ Ah, const __half* __restrict__ Al,
    const __half* __restrict__ Bh, const __half* __restrict__ Bl,
    float* __restrict__ C) {
    extern __shared__ uint32_t dyn[];
    const int tid = threadIdx.x;
    const int w = tid >> 5, lane = tid & 31;
    const int g = lane >> 2, tg = lane & 3;
    const int wm = w >> 2, wn = w & 3;
    const int bm = blockIdx.y * 128, bn = blockIdx.x * 128;

    float acc[4][4][4];
#pragma unroll
    for (int i = 0; i < 4; i++)
#pragma unroll
        for (int j = 0; j < 4; j++)
#pragma unroll
            for (int c = 0; c < 4; c++) acc[i][j][c] = 0.0f;

    const uint32_t sb = smem_u32(dyn);
    g_fill(sb, Ah, Al, Bh, Bl, bm, bn, 0);
    CP_COMMIT();

    for (int i = 0; i < 64; i++) {
        CP_WAIT0();
        __syncthreads();
        if (i + 1 < 64) {
            g_fill(sb + ((i + 1) & 1) * 40960u, Ah, Al, Bh, Bl, bm, bn, (i + 1) * 32);
            CP_COMMIT();
        }
        g_compute(sb + (i & 1) * 40960u, acc, wm, wn, lane);
    }

#pragma unroll
    for (int mf = 0; mf < 4; mf++) {
#pragma unroll
        for (int nf = 0; nf < 4; nf++) {
            const int n = bn + wn * 32 + nf * 8 + tg * 2;
#pragma unroll
            for (int half = 0; half < 2; half++) {
                const int m = bm + wm * 64 + mf * 16 + g + half * 8;
                *(float2*)&C[(size_t)m * HIDDEN + n] =
                    make_float2(acc[mf][nf][half * 2], acc[mf][nf][half * 2 + 1]);
            }
        }
    }
}

// ============================================================================
// RoPE: fp32 q,k [B,H,S,D] -> split fp16 (q scaled by 1/sqrt(D)).
// ============================================================================
__global__ __launch_bounds__(256) void rope_split(
    const float* __restrict__ q, const float* __restrict__ k,
    uint32_t* __restrict__ qh, uint32_t* __restrict__ ql,
    uint32_t* __restrict__ kh, uint32_t* __restrict__ kl) {
    const int gt = blockIdx.x * 256 + threadIdx.x;
    const int row = gt >> 5;
    const int j = gt & 31;
    const int s = row & (SEQ - 1);
    const float sc = 0.08838834764831845f;

    const int p0 = 2 * j, p1 = 2 * j + 1;
    const float i0 = powf(10000.0f, -(float)(2 * p0) / 128.0f);
    const float i1 = powf(10000.0f, -(float)(2 * p1) / 128.0f);
    float sn0, cs0, sn1, cs1;
    sincosf((float)s * i0, &sn0, &cs0);
    sincosf((float)s * i1, &sn1, &cs1);

    const float* pq = q + (size_t)row * HDIM;
    const float* pk = k + (size_t)row * HDIM;
    const float2 qa = *(const float2*)(pq + p0);
    const float2 qb = *(const float2*)(pq + p0 + 64);
    const float2 ka = *(const float2*)(pk + p0);
    const float2 kb = *(const float2*)(pk + p0 + 64);

    const float ql0 = qa.x * cs0 - qb.x * sn0;
    const float ql1 = qa.y * cs1 - qb.y * sn1;
    const float qh0 = qb.x * cs0 + qa.x * sn0;
    const float qh1 = qb.y * cs1 + qa.y * sn1;
    const float kl0 = ka.x * cs0 - kb.x * sn0;
    const float kl1 = ka.y * cs1 - kb.y * sn1;
    const float kh0 = kb.x * cs0 + ka.x * sn0;
    const float kh1 = kb.y * cs1 + ka.y * sn1;

    uint32_t hi, lo;
    const size_t wbase = (size_t)row * 64;
    split2(ql0 * sc, ql1 * sc, hi, lo); qh[wbase + j] = hi;      ql[wbase + j] = lo;
    split2(qh0 * sc, qh1 * sc, hi, lo); qh[wbase + 32 + j] = hi; ql[wbase + 32 + j] = lo;
    split2(kl0, kl1, hi, lo); kh[wbase + j] = hi;      kl[wbase + j] = lo;
    split2(kh0, kh1, hi, lo); kh[wbase + 32 + j] = hi; kl[wbase + 32 + j] = lo;
}

// ============================================================================
// Flash attention v2: P in registers, K+V via ldmatrix, cp.async 2-stage.
// grid (SEQ/128, B*H), 256 threads = 8 warps, warp owns 16 q rows.
// Stage = {Kh,Kl,Vh,Vl}[64 keys x 68 words] = 69632 B; 2 stages = 139264 B.
// ============================================================================
#define AT_STG  69632
#define AT_SMEM (2 * AT_STG)

__global__ __launch_bounds__(256) void flash_attn_h(
    const uint32_t* __restrict__ QH, const uint32_t* __restrict__ QL,
    const uint32_t* __restrict__ KHg, const uint32_t* __restrict__ KLg,
    const uint32_t* __restrict__ VHg, const uint32_t* __restrict__ VLg,
    uint32_t* __restrict__ OH, uint32_t* __restrict__ OL) {
    extern __shared__ uint32_t su[];
    const uint32_t sb = smem_u32(su);

    const int tid = threadIdx.x;
    const int w = tid >> 5, lane = tid & 31;
    const int g = lane >> 2, tg = lane & 3;

    const int bh = blockIdx.y;
    const int q0 = blockIdx.x * 128;
    const size_t kvbase = (size_t)bh * SEQ * 64;

    // ldmatrix lane offsets (stride 68 words = 272 B)
    const uint32_t k_lane = (uint32_t)(((lane & 7) | ((lane >> 1) & 8)) * 272 +
                                       ((lane >> 3) & 1) * 16);
    const uint32_t v_lane = (uint32_t)((lane & 15) * 272 + (lane >> 4) * 16);

    // fill mapping: 4 threads per key row, 4 x 16B per array
    const int frow = tid >> 2, fq4 = tid & 3;

    // ---- prefetch tile 0 ----
    {
        const size_t src = kvbase + (size_t)frow * 64;
#pragma unroll
        for (int i = 0; i < 4; i++) {
            const int wo = fq4 * 4 + i * 16;
            const uint32_t d0 = sb + frow * 272 + wo * 4;
            CP16(d0,          KHg + src + wo);
            CP16(d0 + 17408,  KLg + src + wo);
            CP16(d0 + 34816,  VHg + src + wo);
            CP16(d0 + 52224,  VLg + src + wo);
        }
        CP_COMMIT();
    }

    // ---- Q fragments from gmem ----
    uint32_t qh[8][4], ql[8][4];
    {
        const uint32_t* Qh = QH + ((size_t)bh * SEQ + q0 + w * 16) * 64;
        const uint32_t* Ql = QL + ((size_t)bh * SEQ + q0 + w * 16) * 64;
#pragma unroll
        for (int ks = 0; ks < 8; ks++) {
            const int base = ks * 8 + tg;
            qh[ks][0] = Qh[g * 64 + base];
            qh[ks][1] = Qh[(g + 8) * 64 + base];
            qh[ks][2] = Qh[g * 64 + base + 4];
            qh[ks][3] = Qh[(g + 8) * 64 + base + 4];
            ql[ks][0] = Ql[g * 64 + base];
            ql[ks][1] = Ql[(g + 8) * 64 + base];
            ql[ks][2] = Ql[g * 64 + base + 4];
            ql[ks][3] = Ql[(g + 8) * 64 + base + 4];
        }
    }

    float m0 = -1e30f, m1 = -1e30f, l0 = 0.0f, l1 = 0.0f;
    float oacc[16][4];
#pragma unroll
    for (int nf = 0; nf < 16; nf++)
#pragma unroll
        for (int c = 0; c < 4; c++) oacc[nf][c] = 0.0f;

    for (int kt = 0; kt < SEQ / 64; kt++) {
        CP_WAIT0();
        __syncthreads();   // tile kt visible; all warps done with buffer (kt-1)&1

        if (kt + 1 < SEQ / 64) {
            const uint32_t st = sb + ((kt + 1) & 1) * AT_STG;
            const size_t src = kvbase + (size_t)((kt + 1) * 64 + frow) * 64;
#pragma unroll
            for (int i = 0; i < 4; i++) {
                const int wo = fq4 * 4 + i * 16;
                const uint32_t d0 = st + frow * 272 + wo * 4;
                CP16(d0,         KHg + src + wo);
                CP16(d0 + 17408, KLg + src + wo);
                CP16(d0 + 34816, VHg + src + wo);
                CP16(d0 + 52224, VLg + src + wo);
            }
            CP_COMMIT();
        }

        const uint32_t stg = sb + (kt & 1) * AT_STG;
        const uint32_t sKh = stg, sKl = stg + 17408;
        const uint32_t sVh = stg + 34816, sVl = stg + 52224;

        // ---- S = Q K^T ----
        float sacc[8][4];
#pragma unroll
        for (int nf = 0; nf < 8; nf++)
#pragma unroll
            for (int c = 0; c < 4; c++) sacc[nf][c] = 0.0f;

#pragma unroll
        for (int ks = 0; ks < 8; ks++) {
            const uint32_t ko = ks * 32;
#pragma unroll
            for (int p = 0; p < 4; p++) {          // n-pairs: keys p*16..p*16+15
                uint32_t b4[4], c4[4];
                LDSM_X4(b4[0], b4[1], b4[2], b4[3],
                        sKh + p * 4352 + k_lane + ko);   // 16*272 = 4352
                LDSM_X4(c4[0], c4[1], c4[2], c4[3],
                        sKl + p * 4352 + k_lane + ko);
                mma16816(sacc[2 * p],     qh[ks], b4[0], b4[1]);
                mma16816(sacc[2 * p],     ql[ks], b4[0], b4[1]);
                mma16816(sacc[2 * p],     qh[ks], c4[0], c4[1]);
                mma16816(sacc[2 * p + 1], qh[ks], b4[2], b4[3]);
                mma16816(sacc[2 * p + 1], ql[ks], b4[2], b4[3]);
                mma16816(sacc[2 * p + 1], qh[ks], c4[2], c4[3]);
            }
        }

        // ---- online softmax ----
        float mx0 = -1e30f, mx1 = -1e30f;
#pragma unroll
        for (int nf = 0; nf < 8; nf++) {
            mx0 = fmaxf(mx0, fmaxf(sacc[nf][0], sacc[nf][1]));
            mx1 = fmaxf(mx1, fmaxf(sacc[nf][2], sacc[nf][3]));
        }
        mx0 = fmaxf(mx0, __shfl_xor_sync(0xffffffffu, mx0, 1));
        mx0 = fmaxf(mx0, __shfl_xor_sync(0xffffffffu, mx0, 2));
        mx1 = fmaxf(mx1, __shfl_xor_sync(0xffffffffu, mx1, 1));
        mx1 = fmaxf(mx1, __shfl_xor_sync(0xffffffffu, mx1, 2));

        const float mn0 = fmaxf(m0, mx0);
        const float mn1 = fmaxf(m1, mx1);
        const float fi0 = __expf(m0 - mn0);
        const float fi1 = __expf(m1 - mn1);
        m0 = mn0; m1 = mn1;

        float sum0 = 0.0f, sum1 = 0.0f;
#pragma unroll
        for (int nf = 0; nf < 8; nf++) {
            sacc[nf][0] = __expf(sacc[nf][0] - mn0);
            sacc[nf][1] = __expf(sacc[nf][1] - mn0);
            sacc[nf][2] = __expf(sacc[nf][2] - mn1);
            sacc[nf][3] = __expf(sacc[nf][3] - mn1);
            sum0 += sacc[nf][0] + sacc[nf][1];
            sum1 += sacc[nf][2] + sacc[nf][3];
        }
        sum0 += __shfl_xor_sync(0xffffffffu, sum0, 1);
        sum0 += __shfl_xor_sync(0xffffffffu, sum0, 2);
        sum1 += __shfl_xor_sync(0xffffffffu, sum1, 1);
        sum1 += __shfl_xor_sync(0xffffffffu, sum1, 2);
        l0 = l0 * fi0 + sum0;
        l1 = l1 * fi1 + sum1;

#pragma unroll
        for (int nf = 0; nf < 16; nf++) {
            oacc[nf][0] *= fi0; oacc[nf][1] *= fi0;
            oacc[nf][2] *= fi1; oacc[nf][3] *= fi1;
        }

        // ---- O += P @ V  (P built in registers from sacc) ----
#pragma unroll
        for (int ks = 0; ks < 4; ks++) {           // key chunks of 16
            uint32_t ph[4], pl[4];
            split2(sacc[2 * ks][0],     sacc[2 * ks][1],     ph[0], pl[0]);
            split2(sacc[2 * ks][2],     sacc[2 * ks][3],     ph[1], pl[1]);
            split2(sacc[2 * ks + 1][0], sacc[2 * ks + 1][1], ph[2], pl[2]);
            split2(sacc[2 * ks + 1][2], sacc[2 * ks + 1][3], ph[3], pl[3]);

            const uint32_t krow = ks * 4352;       // ks*16 keys * 272 B
#pragma unroll
            for (int dp = 0; dp < 8; dp++) {       // d-pairs of 16 dims
                uint32_t b4[4], c4[4];
                LDSM_X4T(b4[0], b4[1], b4[2], b4[3],
                         sVh + krow + v_lane + dp * 32);
                LDSM_X4T(c4[0], c4[1], c4[2], c4[3],
                         sVl + krow + v_lane + dp * 32);
                mma16816(oacc[2 * dp],     ph, b4[0], b4[1]);
                mma16816(oacc[2 * dp],     pl, b4[0], b4[1]);
                mma16816(oacc[2 * dp],     ph, c4[0], c4[1]);
                mma16816(oacc[2 * dp + 1], ph, b4[2], b4[3]);
                mma16816(oacc[2 * dp + 1], pl, b4[2], b4[3]);
                mma16816(oacc[2 * dp + 1], ph, c4[2], c4[3]);
            }
        }
    }

    // ---- epilogue: O/l -> split fp16, token-major [B*S, H*D] ----
    const int b = bh >> 4;
    const int h = bh & 15;
    const float il0 = 1.0f / l0;
    const float il1 = 1.0f / l1;
    const int mrow0 = b * SEQ + q0 + w * 16 + g;
#pragma unroll
    for (int nf = 0; nf < 16; nf++) {
        const int cw = h * 64 + nf * 4 + tg;
        uint32_t hi, lo;
        split2(oacc[nf][0] * il0, oacc[nf][1] * il0, hi, lo);
        OH[(size_t)mrow0 * 1024 + cw] = hi;
        OL[(size_t)mrow0 * 1024 + cw] = lo;
        split2(oacc[nf][2] * il1, oacc[nf][3] * il1, hi, lo);
        OH[(size_t)(mrow0 + 8) * 1024 + cw] = hi;
        OL[(size_t)(mrow0 + 8) * 1024 + cw] = lo;
    }
}

// ============================================================================
// kernel_launch
// ============================================================================
extern "C" void kernel_launch(void* const* d_in, const int* in_sizes, int n_in,
                              void* d_out, int out_size) {
    (void)in_sizes; (void)n_in; (void)out_size;
    const float* x  = (const float*)d_in[0];
    const float* wq = (const float*)d_in[1];
    const float* wk = (const float*)d_in[2];
    const float* wv = (const float*)d_in[3];
    const float* wo = (const float*)d_in[4];
    float* out = (float*)d_out;

    void *q, *k, *xh, *xl, *wqh, *wql, *wkh, *wkl, *wvh, *wvl, *woh, *wol;
    void *qh, *ql, *kh, *kl, *vh, *vl, *oh, *ol;
    cudaGetSymbolAddress(&q, g_q);    cudaGetSymbolAddress(&k, g_k);
    cudaGetSymbolAddress(&xh, g_xh);  cudaGetSymbolAddress(&xl, g_xl);
    cudaGetSymbolAddress(&wqh, g_wqh); cudaGetSymbolAddress(&wql, g_wql);
    cudaGetSymbolAddress(&wkh, g_wkh); cudaGetSymbolAddress(&wkl, g_wkl);
    cudaGetSymbolAddress(&wvh, g_wvh); cudaGetSymbolAddress(&wvl, g_wvl);
    cudaGetSymbolAddress(&woh, g_woh); cudaGetSymbolAddress(&wol, g_wol);
    cudaGetSymbolAddress(&qh, g_qh);  cudaGetSymbolAddress(&ql, g_ql);
    cudaGetSymbolAddress(&kh, g_kh);  cudaGetSymbolAddress(&kl, g_kl);
    cudaGetSymbolAddress(&vh, g_vh);  cudaGetSymbolAddress(&vl, g_vl);
    cudaGetSymbolAddress(&oh, g_oh);  cudaGetSymbolAddress(&ol, g_ol);

    cudaFuncSetAttribute(qkv_gemm,
                         cudaFuncAttributeMaxDynamicSharedMemorySize, GK_SMEM);
    cudaFuncSetAttribute(out_gemm,
                         cudaFuncAttributeMaxDynamicSharedMemorySize, GK_SMEM);
    cudaFuncSetAttribute(flash_attn_h,
                         cudaFuncAttributeMaxDynamicSharedMemorySize, AT_SMEM);

    // 1. pre-split x + all weights
    split_kernel<<<(int)(NELEM_X / 4 / 256), 256>>>(
        (const float4*)x, (uint2*)xh, (uint2*)xl, (int)(NELEM_X / 4));
    split4_kernel<<<dim3((int)(NELEM_W / 4 / 256), 4), 256>>>(
        (const float4*)wq, (const float4*)wk, (const float4*)wv, (const float4*)wo,
        (uint2*)wqh, (uint2*)wql, (uint2*)wkh, (uint2*)wkl,
        (uint2*)wvh, (uint2*)wvl, (uint2*)woh, (uint2*)wol, (int)(NELEM_W / 4));

    // 2. fused QKV projections
    qkv_gemm<<<dim3(HIDDEN / 128, MTOK / 128, 3), 256, GK_SMEM>>>(
        (const __half*)xh, (const __half*)xl,
        (const __half*)wqh, (const __half*)wql,
        (const __half*)wkh, (const __half*)wkl,
        (const __half*)wvh, (const __half*)wvl,
        (float*)q, (float*)k, (uint32_t*)vh, (uint32_t*)vl);

    // 3. RoPE + split
    rope_split<<<(BATCH * NHEADS * SEQ * 32) / 256, 256>>>(
        (const float*)q, (const float*)k,
        (uint32_t*)qh, (uint32_t*)ql, (uint32_t*)kh, (uint32_t*)kl);

    // 4. attention
    flash_attn_h<<<dim3(SEQ / 128, BATCH * NHEADS), 256, AT_SMEM>>>(
        (const uint32_t*)qh, (const uint32_t*)ql,
        (const uint32_t*)kh, (const uint32_t*)kl,
        (const uint32_t*)vh, (const uint32_t*)vl,
        (uint32_t*)oh, (uint32_t*)ol);

    // 5. output projection
    out_gemm<<<dim3(HIDDEN / 128, MTOK / 128), 256, GK_SMEM>>>(
        (const __half*)oh, (const __half*)ol,
        (const __half*)woh, (const __half*)wol, out);
}

// round 10
// speedup vs baseline: 1.0011x; 1.0011x over previous
#include <cuda_runtime.h>
#include <cuda_fp16.h>
#include <math.h>
#include <stdint.h>

#define HIDDEN  2048
#define NHEADS  16
#define HDIM    128
#define BATCH   2
#define SEQ     2048
#define MTOK    (BATCH * SEQ)   // 4096

#define NELEM_X ((size_t)MTOK * HIDDEN)     // 8388608
#define NELEM_W ((size_t)HIDDEN * HIDDEN)   // 4194304

// ---------------- scratch (static device globals) ---------------------------
__device__ __align__(16) float  g_q[NELEM_X];
__device__ __align__(16) float  g_k[NELEM_X];
__device__ __align__(16) __half g_xh[NELEM_X],  g_xl[NELEM_X];
__device__ __align__(16) __half g_wqh[NELEM_W], g_wql[NELEM_W];
__device__ __align__(16) __half g_wkh[NELEM_W], g_wkl[NELEM_W];
__device__ __align__(16) __half g_wvh[NELEM_W], g_wvl[NELEM_W];
__device__ __align__(16) __half g_woh[NELEM_W], g_wol[NELEM_W];
__device__ __align__(16) __half g_qh[NELEM_X],  g_ql[NELEM_X];
__device__ __align__(16) __half g_kh[NELEM_X],  g_kl[NELEM_X];
__device__ __align__(16) __half g_vh[NELEM_X],  g_vl[NELEM_X];
__device__ __align__(16) __half g_oh[NELEM_X],  g_ol[NELEM_X];

// ---------------- helpers ----------------------------------------------------
__device__ __forceinline__ void split2(float x, float y, uint32_t& hi, uint32_t& lo) {
    __half2 h = __float22half2_rn(make_float2(x, y));
    float2 b = __half22float2(h);
    __half2 l = __float22half2_rn(make_float2(x - b.x, y - b.y));
    hi = *(uint32_t*)&h;
    lo = *(uint32_t*)&l;
}
__device__ __forceinline__ void mma16816(float* c, const uint32_t* a,
                                         uint32_t b0, uint32_t b1) {
    asm volatile(
        "mma.sync.aligned.m16n8k16.row.col.f32.f16.f16.f32 "
        "{%0,%1,%2,%3}, {%4,%5,%6,%7}, {%8,%9}, {%0,%1,%2,%3};\n"
        : "+f"(c[0]), "+f"(c[1]), "+f"(c[2]), "+f"(c[3])
        : "r"(a[0]), "r"(a[1]), "r"(a[2]), "r"(a[3]), "r"(b0), "r"(b1));
}
__device__ __forceinline__ uint32_t smem_u32(const void* p) {
    uint32_t a;
    asm("{ .reg .u64 t; cvta.to.shared.u64 t, %1; cvt.u32.u64 %0, t; }"
        : "=r"(a) : "l"(p));
    return a;
}
#define CP16(dst, src) \
    asm volatile("cp.async.cg.shared.global [%0], [%1], 16;" \
                 :: "r"(dst), "l"(src) : "memory")
#define CP_COMMIT() asm volatile("cp.async.commit_group;" ::: "memory")
#define CP_WAIT0()  asm volatile("cp.async.wait_group 0;"  ::: "memory")

#define LDSM_X4(r0, r1, r2, r3, a)                                          \
    asm volatile("ldmatrix.sync.aligned.m8n8.x4.shared.b16 {%0,%1,%2,%3}, [%4];" \
                 : "=r"(r0), "=r"(r1), "=r"(r2), "=r"(r3) : "r"(a))
#define LDSM_X4T(r0, r1, r2, r3, a)                                         \
    asm volatile("ldmatrix.sync.aligned.m8n8.x4.trans.shared.b16 {%0,%1,%2,%3}, [%4];" \
                 : "=r"(r0), "=r"(r1), "=r"(r2), "=r"(r3) : "r"(a))

// ============================================================================
// split kernels
// ============================================================================
__global__ __launch_bounds__(256) void split_kernel(const float4* __restrict__ src,
                                                    uint2* __restrict__ hi,
                                                    uint2* __restrict__ lo, int n4) {
    const int i = blockIdx.x * 256 + threadIdx.x;
    if (i >= n4) return;
    const float4 v = src[i];
    uint32_t h0, l0, h1, l1;
    split2(v.x, v.y, h0, l0);
    split2(v.z, v.w, h1, l1);
    hi[i] = make_uint2(h0, h1);
    lo[i] = make_uint2(l0, l1);
}

// all 4 weights in one launch (z selects)
__global__ __launch_bounds__(256) void split4_kernel(
    const float4* __restrict__ s0, const float4* __restrict__ s1,
    const float4* __restrict__ s2, const float4* __restrict__ s3,
    uint2* __restrict__ h0, uint2* __restrict__ l0,
    uint2* __restrict__ h1, uint2* __restrict__ l1,
    uint2* __restrict__ h2, uint2* __restrict__ l2,
    uint2* __restrict__ h3, uint2* __restrict__ l3, int n4) {
    const int i = blockIdx.x * 256 + threadIdx.x;
    if (i >= n4) return;
    const int z = blockIdx.y;
    const float4* src = (z == 0) ? s0 : (z == 1) ? s1 : (z == 2) ? s2 : s3;
    uint2* hi = (z == 0) ? h0 : (z == 1) ? h1 : (z == 2) ? h2 : h3;
    uint2* lo = (z == 0) ? l0 : (z == 1) ? l1 : (z == 2) ? l2 : l3;
    const float4 v = src[i];
    uint32_t a0, b0, a1, b1;
    split2(v.x, v.y, a0, b0);
    split2(v.z, v.w, a1, b1);
    hi[i] = make_uint2(a0, a1);
    lo[i] = make_uint2(b0, b1);
}

// ============================================================================
// GEMM core (NT): 128x128 tile, BK=32, 256 threads, cp.async double-buffered,
// fragment loads via ldmatrix.x4.
// smem stage = {Ah,Al,Bh,Bl} x 128row x 20 words = 40960 B; 2 stages.
// ============================================================================
#define GK_SMEM 81920

__device__ __forceinline__ void g_fill(uint32_t sb,
                                       const __half* __restrict__ Ah,
                                       const __half* __restrict__ Al,
                                       const __half* __restrict__ Bh,
                                       const __half* __restrict__ Bl,
                                       int bm, int bn, int k0) {
    const int tid = threadIdx.x;
    const int row = tid >> 1, hf = tid & 1;
    const uint32_t off = (uint32_t)(row * 20 + hf * 8) * 4;
    const size_t ra = ((size_t)(bm + row) << 11) + k0 + hf * 16;
    const size_t rb = ((size_t)(bn + row) << 11) + k0 + hf * 16;
    CP16(sb + off,         Ah + ra); CP16(sb + off + 16,         Ah + ra + 8);
    CP16(sb + 10240 + off, Al + ra); CP16(sb + 10240 + off + 16, Al + ra + 8);
    CP16(sb + 20480 + off, Bh + rb); CP16(sb + 20480 + off + 16, Bh + rb + 8);
    CP16(sb + 30720 + off, Bl + rb); CP16(sb + 30720 + off + 16, Bl + rb + 8);
}

__device__ __forceinline__ void g_compute(uint32_t s, float acc[4][4][4],
                                          int wm, int wn, int lane) {
    // A x4: lanes 0-15 rows (l&15) @k0-chunk, lanes 16-31 same rows @k8-chunk
    const uint32_t aln = (uint32_t)((lane & 15) * 80 + (lane >> 4) * 16);
    // B x4: lanes 0-7 n0-7@k0, 8-15 n0-7@k8, 16-23 n8-15@k0, 24-31 n8-15@k8
    const uint32_t bln = (uint32_t)(((lane & 7) | ((lane >> 1) & 8)) * 80 +
                                    ((lane >> 3) & 1) * 16);
    const uint32_t sAh = s + (uint32_t)(wm * 64 * 80) + aln;
    const uint32_t sAl = sAh + 10240;
    const uint32_t sBh = s + 20480 + (uint32_t)(wn * 32 * 80) + bln;
    const uint32_t sBl = sBh + 10240;

#pragma unroll
    for (int ks = 0; ks < 2; ks++) {
        const uint32_t ko = ks * 32;
        uint32_t ah[4][4], al[4][4], bh[2][4], bl[2][4];
#pragma unroll
        for (int mf = 0; mf < 4; mf++) {
            LDSM_X4(ah[mf][0], ah[mf][1], ah[mf][2], ah[mf][3],
                    sAh + mf * 1280 + ko);
            LDSM_X4(al[mf][0], al[mf][1], al[mf][2], al[mf][3],
                    sAl + mf * 1280 + ko);
        }
#pragma unroll
        for (int p = 0; p < 2; p++) {
            LDSM_X4(bh[p][0], bh[p][1], bh[p][2], bh[p][3], sBh + p * 1280 + ko);
            LDSM_X4(bl[p][0], bl[p][1], bl[p][2], bl[p][3], sBl + p * 1280 + ko);
        }
#pragma unroll
        for (int p = 0; p < 2; p++) {
#pragma unroll
            for (int hh = 0; hh < 2; hh++) {
                const int nf = p * 2 + hh;
                const uint32_t b0 = bh[p][hh * 2], b1 = bh[p][hh * 2 + 1];
                const uint32_t c0 = bl[p][hh * 2], c1 = bl[p][hh * 2 + 1];
#pragma unroll
                for (int mf = 0; mf < 4; mf++) {
                    mma16816(acc[mf][nf], ah[mf], b0, b1);
                    mma16816(acc[mf][nf], al[mf], b0, b1);
                    mma16816(acc[mf][nf], ah[mf], c0, c1);
                }
            }
        }
    }
}

// Fused QKV GEMM: z=0 -> q fp32 [B,H,S,D]; z=1 -> k fp32; z=2 -> v split fp16.
__global__ __launch_bounds__(256, 2) void qkv_gemm(
    const __half* __restrict__ xh, const __half* __restrict__ xl,
    const __half* __restrict__ wqh, const __half* __restrict__ wql,
    const __half* __restrict__ wkh, const __half* __restrict__ wkl,
    const __half* __restrict__ wvh, const __half* __restrict__ wvl,
    float* __restrict__ q, float* __restrict__ k,
    uint32_t* __restrict__ vh, uint32_t* __restrict__ vl) {
    extern __shared__ uint32_t dyn[];
    const int tid = threadIdx.x;
    const int w = tid >> 5, lane = tid & 31;
    const int g = lane >> 2, tg = lane & 3;
    const int wm = w >> 2, wn = w & 3;
    const int bm = blockIdx.y * 128, bn = blockIdx.x * 128;
    const int z = blockIdx.z;

    const __half* Bh = (z == 0) ? wqh : (z == 1) ? wkh : wvh;
    const __half* Bl = (z == 0) ? wql : (z == 1) ? wkl : wvl;

    float acc[4][4][4];
#pragma unroll
    for (int i = 0; i < 4; i++)
#pragma unroll
        for (int j = 0; j < 4; j++)
#pragma unroll
            for (int c = 0; c < 4; c++) acc[i][j][c] = 0.0f;

    const uint32_t sb = smem_u32(dyn);
    g_fill(sb, xh, xl, Bh, Bl, bm, bn, 0);
    CP_COMMIT();

    for (int i = 0; i < 64; i++) {
        CP_WAIT0();
        __syncthreads();
        if (i + 1 < 64) {
            g_fill(sb + ((i + 1) & 1) * 40960u, xh, xl, Bh, Bl, bm, bn, (i + 1) * 32);
            CP_COMMIT();
        }
        g_compute(sb + (i & 1) * 40960u, acc, wm, wn, lane);
    }

#pragma unroll
    for (int mf = 0; mf < 4; mf++) {
#pragma unroll
        for (int nf = 0; nf < 4; nf++) {
            const int n = bn + wn * 32 + nf * 8 + tg * 2;
            const int h = n >> 7, d = n & 127;
            const int m0 = bm + wm * 64 + mf * 16 + g;
            const int b = m0 >> 11, s0 = m0 & (SEQ - 1);
            if (z == 2) {
                const size_t widx =
                    (((size_t)(b * NHEADS + h) * SEQ + s0) << 6) + (d >> 1);
                uint32_t hi, lo;
                split2(acc[mf][nf][0], acc[mf][nf][1], hi, lo);
                vh[widx] = hi; vl[widx] = lo;
                split2(acc[mf][nf][2], acc[mf][nf][3], hi, lo);
                vh[widx + 512] = hi; vl[widx + 512] = lo;
            } else {
                float* C = (z == 0) ? q : k;
                const size_t base =
                    (((size_t)(b * NHEADS + h) * SEQ + s0) << 7) + d;
                *(float2*)&C[base] = make_float2(acc[mf][nf][0], acc[mf][nf][1]);
                *(float2*)&C[base + (8u << 7)] =
                    make_float2(acc[mf][nf][2], acc[mf][nf][3]);
            }
        }
    }
}

__global__ __launch_bounds__(256, 2) void out_gemm(
    const __half* __restrict__ Ah, const __half* __restrict__ Al,
    const __half* __restrict__ Bh, const __half* __restrict__ Bl,
    float* __restrict__ C) {
    extern __shared__ uint32_t dyn[];
    const int tid = threadIdx.x;
    const int w = tid >> 5, lane = tid & 31;
    const int g = lane >> 2, tg = lane & 3;
    const int wm = w >> 2, wn = w & 3;
    const int bm = blockIdx.y * 128, bn = blockIdx.x * 128;

    float acc[4][4][4];
#pragma unroll
    for (int i = 0; i < 4; i++)
#pragma unroll
        for (int j = 0; j < 4; j++)
#pragma unroll
            for (int c = 0; c < 4; c++) acc[i][j][c] = 0.0f;

    const uint32_t sb = smem_u32(dyn);
    g_fill(sb, Ah, Al, Bh, Bl, bm, bn, 0);
    CP_COMMIT();

    for (int i = 0; i < 64; i++) {
        CP_WAIT0();
        __syncthreads();
        if (i + 1 < 64) {
            g_fill(sb + ((i + 1) & 1) * 40960u, Ah, Al, Bh, Bl, bm, bn, (i + 1) * 32);
            CP_COMMIT();
        }
        g_compute(sb + (i & 1) * 40960u, acc, wm, wn, lane);
    }

#pragma unroll
    for (int mf = 0; mf < 4; mf++) {
#pragma unroll
        for (int nf = 0; nf < 4; nf++) {
            const int n = bn + wn * 32 + nf * 8 + tg * 2;
#pragma unroll
            for (int half = 0; half < 2; half++) {
                const int m = bm + wm * 64 + mf * 16 + g + half * 8;
                *(float2*)&C[(size_t)m * HIDDEN + n] =
                    make_float2(acc[mf][nf][half * 2], acc[mf][nf][half * 2 + 1]);
            }
        }
    }
}

// ============================================================================
// RoPE: fp32 q,k [B,H,S,D] -> split fp16 (q scaled by 1/sqrt(D)).
// ============================================================================
__global__ __launch_bounds__(256) void rope_split(
    const float* __restrict__ q, const float* __restrict__ k,
    uint32_t* __restrict__ qh, uint32_t* __restrict__ ql,
    uint32_t* __restrict__ kh, uint32_t* __restrict__ kl) {
    const int gt = blockIdx.x * 256 + threadIdx.x;
    const int row = gt >> 5;
    const int j = gt & 31;
    const int s = row & (SEQ - 1);
    const float sc = 0.08838834764831845f;

    const int p0 = 2 * j, p1 = 2 * j + 1;
    const float i0 = powf(10000.0f, -(float)(2 * p0) / 128.0f);
    const float i1 = powf(10000.0f, -(float)(2 * p1) / 128.0f);
    float sn0, cs0, sn1, cs1;
    sincosf((float)s * i0, &sn0, &cs0);
    sincosf((float)s * i1, &sn1, &cs1);

    const float* pq = q + (size_t)row * HDIM;
    const float* pk = k + (size_t)row * HDIM;
    const float2 qa = *(const float2*)(pq + p0);
    const float2 qb = *(const float2*)(pq + p0 + 64);
    const float2 ka = *(const float2*)(pk + p0);
    const float2 kb = *(const float2*)(pk + p0 + 64);

    const float ql0 = qa.x * cs0 - qb.x * sn0;
    const float ql1 = qa.y * cs1 - qb.y * sn1;
    const float qh0 = qb.x * cs0 + qa.x * sn0;
    const float qh1 = qb.y * cs1 + qa.y * sn1;
    const float kl0 = ka.x * cs0 - kb.x * sn0;
    const float kl1 = ka.y * cs1 - kb.y * sn1;
    const float kh0 = kb.x * cs0 + ka.x * sn0;
    const float kh1 = kb.y * cs1 + ka.y * sn1;

    uint32_t hi, lo;
    const size_t wbase = (size_t)row * 64;
    split2(ql0 * sc, ql1 * sc, hi, lo); qh[wbase + j] = hi;      ql[wbase + j] = lo;
    split2(qh0 * sc, qh1 * sc, hi, lo); qh[wbase + 32 + j] = hi; ql[wbase + 32 + j] = lo;
    split2(kl0, kl1, hi, lo); kh[wbase + j] = hi;      kl[wbase + j] = lo;
    split2(kh0, kh1, hi, lo); kh[wbase + 32 + j] = hi; kl[wbase + 32 + j] = lo;
}

// ============================================================================
// Flash attention v2: P in registers, K+V via ldmatrix, cp.async 2-stage.
// grid (SEQ/128, B*H), 256 threads = 8 warps, warp owns 16 q rows.
// Stage = {Kh,Kl,Vh,Vl}[64 keys x 68 words] = 69632 B; 2 stages = 139264 B.
// ============================================================================
#define AT_STG  69632
#define AT_SMEM (2 * AT_STG)

__global__ __launch_bounds__(256) void flash_attn_h(
    const uint32_t* __restrict__ QH, const uint32_t* __restrict__ QL,
    const uint32_t* __restrict__ KHg, const uint32_t* __restrict__ KLg,
    const uint32_t* __restrict__ VHg, const uint32_t* __restrict__ VLg,
    uint32_t* __restrict__ OH, uint32_t* __restrict__ OL) {
    extern __shared__ uint32_t su[];
    const uint32_t sb = smem_u32(su);

    const int tid = threadIdx.x;
    const int w = tid >> 5, lane = tid & 31;
    const int g = lane >> 2, tg = lane & 3;

    const int bh = blockIdx.y;
    const int q0 = blockIdx.x * 128;
    const size_t kvbase = (size_t)bh * SEQ * 64;

    // ldmatrix lane offsets (stride 68 words = 272 B)
    const uint32_t k_lane = (uint32_t)(((lane & 7) | ((lane >> 1) & 8)) * 272 +
                                       ((lane >> 3) & 1) * 16);
    const uint32_t v_lane = (uint32_t)((lane & 15) * 272 + (lane >> 4) * 16);

    // fill mapping: 4 threads per key row, 4 x 16B per array
    const int frow = tid >> 2, fq4 = tid & 3;

    // ---- prefetch tile 0 ----
    {
        const size_t src = kvbase + (size_t)frow * 64;
#pragma unroll
        for (int i = 0; i < 4; i++) {
            const int wo = fq4 * 4 + i * 16;
            const uint32_t d0 = sb + frow * 272 + wo * 4;
            CP16(d0,          KHg + src + wo);
            CP16(d0 + 17408,  KLg + src + wo);
            CP16(d0 + 34816,  VHg + src + wo);
            CP16(d0 + 52224,  VLg + src + wo);
        }
        CP_COMMIT();
    }

    // ---- Q fragments from gmem ----
    uint32_t qh[8][4], ql[8][4];
    {
        const uint32_t* Qh = QH + ((size_t)bh * SEQ + q0 + w * 16) * 64;
        const uint32_t* Ql = QL + ((size_t)bh * SEQ + q0 + w * 16) * 64;
#pragma unroll
        for (int ks = 0; ks < 8; ks++) {
            const int base = ks * 8 + tg;
            qh[ks][0] = Qh[g * 64 + base];
            qh[ks][1] = Qh[(g + 8) * 64 + base];
            qh[ks][2] = Qh[g * 64 + base + 4];
            qh[ks][3] = Qh[(g + 8) * 64 + base + 4];
            ql[ks][0] = Ql[g * 64 + base];
            ql[ks][1] = Ql[(g + 8) * 64 + base];
            ql[ks][2] = Ql[g * 64 + base + 4];
            ql[ks][3] = Ql[(g + 8) * 64 + base + 4];
        }
    }

    float m0 = -1e30f, m1 = -1e30f, l0 = 0.0f, l1 = 0.0f;
    float oacc[16][4];
#pragma unroll
    for (int nf = 0; nf < 16; nf++)
#pragma unroll
        for (int c = 0; c < 4; c++) oacc[nf][c] = 0.0f;

    for (int kt = 0; kt < SEQ / 64; kt++) {
        CP_WAIT0();
        __syncthreads();   // tile kt visible; all warps done with buffer (kt-1)&1

        if (kt + 1 < SEQ / 64) {
            const uint32_t st = sb + ((kt + 1) & 1) * AT_STG;
            const size_t src = kvbase + (size_t)((kt + 1) * 64 + frow) * 64;
#pragma unroll
            for (int i = 0; i < 4; i++) {
                const int wo = fq4 * 4 + i * 16;
                const uint32_t d0 = st + frow * 272 + wo * 4;
                CP16(d0,         KHg + src + wo);
                CP16(d0 + 17408, KLg + src + wo);
                CP16(d0 + 34816, VHg + src + wo);
                CP16(d0 + 52224, VLg + src + wo);
            }
            CP_COMMIT();
        }

        const uint32_t stg = sb + (kt & 1) * AT_STG;
        const uint32_t sKh = stg, sKl = stg + 17408;
        const uint32_t sVh = stg + 34816, sVl = stg + 52224;

        // ---- S = Q K^T ----
        float sacc[8][4];
#pragma unroll
        for (int nf = 0; nf < 8; nf++)
#pragma unroll
            for (int c = 0; c < 4; c++) sacc[nf][c] = 0.0f;

#pragma unroll
        for (int ks = 0; ks < 8; ks++) {
            const uint32_t ko = ks * 32;
#pragma unroll
            for (int p = 0; p < 4; p++) {          // n-pairs: keys p*16..p*16+15
                uint32_t b4[4], c4[4];
                LDSM_X4(b4[0], b4[1], b4[2], b4[3],
                        sKh + p * 4352 + k_lane + ko);   // 16*272 = 4352
                LDSM_X4(c4[0], c4[1], c4[2], c4[3],
                        sKl + p * 4352 + k_lane + ko);
                mma16816(sacc[2 * p],     qh[ks], b4[0], b4[1]);
                mma16816(sacc[2 * p],     ql[ks], b4[0], b4[1]);
                mma16816(sacc[2 * p],     qh[ks], c4[0], c4[1]);
                mma16816(sacc[2 * p + 1], qh[ks], b4[2], b4[3]);
                mma16816(sacc[2 * p + 1], ql[ks], b4[2], b4[3]);
                mma16816(sacc[2 * p + 1], qh[ks], c4[2], c4[3]);
            }
        }

        // ---- online softmax ----
        float mx0 = -1e30f, mx1 = -1e30f;
#pragma unroll
        for (int nf = 0; nf < 8; nf++) {
            mx0 = fmaxf(mx0, fmaxf(sacc[nf][0], sacc[nf][1]));
            mx1 = fmaxf(mx1, fmaxf(sacc[nf][2], sacc[nf][3]));
        }
        mx0 = fmaxf(mx0, __shfl_xor_sync(0xffffffffu, mx0, 1));
        mx0 = fmaxf(mx0, __shfl_xor_sync(0xffffffffu, mx0, 2));
        mx1 = fmaxf(mx1, __shfl_xor_sync(0xffffffffu, mx1, 1));
        mx1 = fmaxf(mx1, __shfl_xor_sync(0xffffffffu, mx1, 2));

        const float mn0 = fmaxf(m0, mx0);
        const float mn1 = fmaxf(m1, mx1);
        const float fi0 = __expf(m0 - mn0);
        const float fi1 = __expf(m1 - mn1);
        m0 = mn0; m1 = mn1;

        float sum0 = 0.0f, sum1 = 0.0f;
#pragma unroll
        for (int nf = 0; nf < 8; nf++) {
            sacc[nf][0] = __expf(sacc[nf][0] - mn0);
            sacc[nf][1] = __expf(sacc[nf][1] - mn0);
            sacc[nf][2] = __expf(sacc[nf][2] - mn1);
            sacc[nf][3] = __expf(sacc[nf][3] - mn1);
            sum0 += sacc[nf][0] + sacc[nf][1];
            sum1 += sacc[nf][2] + sacc[nf][3];
        }
        sum0 += __shfl_xor_sync(0xffffffffu, sum0, 1);
        sum0 += __shfl_xor_sync(0xffffffffu, sum0, 2);
        sum1 += __shfl_xor_sync(0xffffffffu, sum1, 1);
        sum1 += __shfl_xor_sync(0xffffffffu, sum1, 2);
        l0 = l0 * fi0 + sum0;
        l1 = l1 * fi1 + sum1;

#pragma unroll
        for (int nf = 0; nf < 16; nf++) {
            oacc[nf][0] *= fi0; oacc[nf][1] *= fi0;
            oacc[nf][2] *= fi1; oacc[nf][3] *= fi1;
        }

        // ---- O += P @ V  (P built in registers from sacc) ----
#pragma unroll
        for (int ks = 0; ks < 4; ks++) {           // key chunks of 16
            uint32_t ph[4], pl[4];
            split2(sacc[2 * ks][0],     sacc[2 * ks][1],     ph[0], pl[0]);
            split2(sacc[2 * ks][2],     sacc[2 * ks][3],     ph[1], pl[1]);
            split2(sacc[2 * ks + 1][0], sacc[2 * ks + 1][1], ph[2], pl[2]);
            split2(sacc[2 * ks + 1][2], sacc[2 * ks + 1][3], ph[3], pl[3]);

            const uint32_t krow = ks * 4352;       // ks*16 keys * 272 B
#pragma unroll
            for (int dp = 0; dp < 8; dp++) {       // d-pairs of 16 dims
                uint32_t b4[4], c4[4];
                LDSM_X4T(b4[0], b4[1], b4[2], b4[3],
                         sVh + krow + v_lane + dp * 32);
                LDSM_X4T(c4[0], c4[1], c4[2], c4[3],
                         sVl + krow + v_lane + dp * 32);
                mma16816(oacc[2 * dp],     ph, b4[0], b4[1]);
                mma16816(oacc[2 * dp],     pl, b4[0], b4[1]);
                mma16816(oacc[2 * dp],     ph, c4[0], c4[1]);
                mma16816(oacc[2 * dp + 1], ph, b4[2], b4[3]);
                mma16816(oacc[2 * dp + 1], pl, b4[2], b4[3]);
                mma16816(oacc[2 * dp + 1], ph, c4[2], c4[3]);
            }
        }
    }

    // ---- epilogue: O/l -> split fp16, token-major [B*S, H*D] ----
    const int b = bh >> 4;
    const int h = bh & 15;
    const float il0 = 1.0f / l0;
    const float il1 = 1.0f / l1;
    const int mrow0 = b * SEQ + q0 + w * 16 + g;
#pragma unroll
    for (int nf = 0; nf < 16; nf++) {
        const int cw = h * 64 + nf * 4 + tg;
        uint32_t hi, lo;
        split2(oacc[nf][0] * il0, oacc[nf][1] * il0, hi, lo);
        OH[(size_t)mrow0 * 1024 + cw] = hi;
        OL[(size_t)mrow0 * 1024 + cw] = lo;
        split2(oacc[nf][2] * il1, oacc[nf][3] * il1, hi, lo);
        OH[(size_t)(mrow0 + 8) * 1024 + cw] = hi;
        OL[(size_t)(mrow0 + 8) * 1024 + cw] = lo;
    }
}

// ============================================================================
// kernel_launch
// ============================================================================
extern "C" void kernel_launch(void* const* d_in, const int* in_sizes, int n_in,
                              void* d_out, int out_size) {
    (void)in_sizes; (void)n_in; (void)out_size;
    const float* x  = (const float*)d_in[0];
    const float* wq = (const float*)d_in[1];
    const float* wk = (const float*)d_in[2];
    const float* wv = (const float*)d_in[3];
    const float* wo = (const float*)d_in[4];
    float* out = (float*)d_out;

    void *q, *k, *xh, *xl, *wqh, *wql, *wkh, *wkl, *wvh, *wvl, *woh, *wol;
    void *qh, *ql, *kh, *kl, *vh, *vl, *oh, *ol;
    cudaGetSymbolAddress(&q, g_q);    cudaGetSymbolAddress(&k, g_k);
    cudaGetSymbolAddress(&xh, g_xh);  cudaGetSymbolAddress(&xl, g_xl);
    cudaGetSymbolAddress(&wqh, g_wqh); cudaGetSymbolAddress(&wql, g_wql);
    cudaGetSymbolAddress(&wkh, g_wkh); cudaGetSymbolAddress(&wkl, g_wkl);
    cudaGetSymbolAddress(&wvh, g_wvh); cudaGetSymbolAddress(&wvl, g_wvl);
    cudaGetSymbolAddress(&woh, g_woh); cudaGetSymbolAddress(&wol, g_wol);
    cudaGetSymbolAddress(&qh, g_qh);  cudaGetSymbolAddress(&ql, g_ql);
    cudaGetSymbolAddress(&kh, g_kh);  cudaGetSymbolAddress(&kl, g_kl);
    cudaGetSymbolAddress(&vh, g_vh);  cudaGetSymbolAddress(&vl, g_vl);
    cudaGetSymbolAddress(&oh, g_oh);  cudaGetSymbolAddress(&ol, g_ol);

    cudaFuncSetAttribute(qkv_gemm,
                         cudaFuncAttributeMaxDynamicSharedMemorySize, GK_SMEM);
    cudaFuncSetAttribute(out_gemm,
                         cudaFuncAttributeMaxDynamicSharedMemorySize, GK_SMEM);
    cudaFuncSetAttribute(flash_attn_h,
                         cudaFuncAttributeMaxDynamicSharedMemorySize, AT_SMEM);

    // 1. pre-split x + all weights
    split_kernel<<<(int)(NELEM_X / 4 / 256), 256>>>(
        (const float4*)x, (uint2*)xh, (uint2*)xl, (int)(NELEM_X / 4));
    split4_kernel<<<dim3((int)(NELEM_W / 4 / 256), 4), 256>>>(
        (const float4*)wq, (const float4*)wk, (const float4*)wv, (const float4*)wo,
        (uint2*)wqh, (uint2*)wql, (uint2*)wkh, (uint2*)wkl,
        (uint2*)wvh, (uint2*)wvl, (uint2*)woh, (uint2*)wol, (int)(NELEM_W / 4));

    // 2. fused QKV projections
    qkv_gemm<<<dim3(HIDDEN / 128, MTOK / 128, 3), 256, GK_SMEM>>>(
        (const __half*)xh, (const __half*)xl,
        (const __half*)wqh, (const __half*)wql,
        (const __half*)wkh, (const __half*)wkl,
        (const __half*)wvh, (const __half*)wvl,
        (float*)q, (float*)k, (uint32_t*)vh, (uint32_t*)vl);

    // 3. RoPE + split
    rope_split<<<(BATCH * NHEADS * SEQ * 32) / 256, 256>>>(
        (const float*)q, (const float*)k,
        (uint32_t*)qh, (uint32_t*)ql, (uint32_t*)kh, (uint32_t*)kl);

    // 4. attention
    flash_attn_h<<<dim3(SEQ / 128, BATCH * NHEADS), 256, AT_SMEM>>>(
        (const uint32_t*)qh, (const uint32_t*)ql,
        (const uint32_t*)kh, (const uint32_t*)kl,
        (const uint32_t*)vh, (const uint32_t*)vl,
        (uint32_t*)oh, (uint32_t*)ol);

    // 5. output projection
    out_gemm<<<dim3(HIDDEN / 128, MTOK / 128), 256, GK_SMEM>>>(
        (const __half*)oh, (const __half*)ol,
        (const __half*)woh, (const __half*)wol, out);
}